// round 15
// baseline (speedup 1.0000x reference)
#include <cuda_runtime.h>
#include <cuda_bf16.h>
#include <cstdint>

#define Bb 8
#define Cc 512
#define Ci 256
#define Nn 4096
#define Mm 1024

using bf16 = __nv_bfloat16;

// ---------------- device scratch (static; no allocation allowed) ----------------
__device__ __align__(128) bf16 d_xT_h[(size_t)Bb*Nn*Cc], d_xT_l[(size_t)Bb*Nn*Cc];   // x^T split [b][n][c]
__device__ __align__(128) bf16 d_wcat_h[3*Ci*Cc], d_wcat_l[3*Ci*Cc];                  // theta|phi|g weights
__device__ __align__(128) bf16 d_ww_h [Cc*Ci], d_ww_l [Cc*Ci];
__device__ __align__(128) bf16 d_xth_h [(size_t)Bb*Nn*Ci], d_xth_l [(size_t)Bb*Nn*Ci]; // theta [b][n][ci]
__device__ __align__(128) bf16 d_xphi_h[(size_t)Bb*Mm*Ci], d_xphi_l[(size_t)Bb*Mm*Ci]; // phi pooled [b][m][ci]
__device__ __align__(128) bf16 d_xg_h  [(size_t)Bb*Ci*Mm], d_xg_l  [(size_t)Bb*Ci*Mm]; // g pooled^T [b][ci][m]
__device__ __align__(128) bf16 d_u_h   [(size_t)Bb*Nn*Mm], d_u_l[(size_t)Bb*Nn*Mm];   // u = exp(logit-40), split
__device__ __align__(128) float d_spart[(size_t)Bb*Nn*8];                               // row partial sums (8 j-tiles)
__device__ __align__(128) bf16 d_y_h   [(size_t)Bb*Nn*Ci], d_y_l[(size_t)Bb*Nn*Ci];    // y [b][n][ci]

// ---------------- PTX helpers (baseline sm_80+ ISA only) ----------------
__device__ __forceinline__ uint32_t smem_u32(const void* p) {
    uint32_t a;
    asm("{ .reg .u64 t; cvta.to.shared.u64 t, %1; cvt.u32.u64 %0, t; }" : "=r"(a) : "l"(p));
    return a;
}
__device__ __forceinline__ void cp16(uint32_t dst, const void* src) {
    asm volatile("cp.async.cg.shared.global [%0], [%1], 16;" :: "r"(dst), "l"(src));
}
#define CP_COMMIT() asm volatile("cp.async.commit_group;" ::: "memory")
#define CP_WAIT(n)  asm volatile("cp.async.wait_group %0;" :: "n"(n) : "memory")

__device__ __forceinline__ void mma16816(float* c, const uint32_t* a, const uint32_t* b) {
    asm volatile("mma.sync.aligned.m16n8k16.row.col.f32.bf16.bf16.f32 "
                 "{%0,%1,%2,%3}, {%4,%5,%6,%7}, {%8,%9}, {%0,%1,%2,%3};"
                 : "+f"(c[0]), "+f"(c[1]), "+f"(c[2]), "+f"(c[3])
                 : "r"(a[0]), "r"(a[1]), "r"(a[2]), "r"(a[3]), "r"(b[0]), "r"(b[1]));
}
__device__ __forceinline__ void ldsm4(uint32_t addr, uint32_t& r0, uint32_t& r1,
                                      uint32_t& r2, uint32_t& r3) {
    asm volatile("ldmatrix.sync.aligned.m8n8.x4.shared.b16 {%0,%1,%2,%3}, [%4];"
                 : "=r"(r0), "=r"(r1), "=r"(r2), "=r"(r3) : "r"(addr));
}
// pack (v0,v1) -> bf16x2 word (lo = bf16(v0), hi = bf16(v1)), rn rounding
__device__ __forceinline__ uint32_t pack_bf16x2(float v0, float v1) {
    uint32_t r;
    asm("cvt.rn.bf16x2.f32 %0, %1, %2;" : "=r"(r) : "f"(v1), "f"(v0));
    return r;
}
// paired hi/lo split: 6 ops/pair (bf16 == top 16 bits of fp32, reconstruct via shift/mask)
__device__ __forceinline__ void split_pair(float v0, float v1, uint32_t& h, uint32_t& l) {
    h = pack_bf16x2(v0, v1);
    const float h0 = __uint_as_float(h << 16);
    const float h1 = __uint_as_float(h & 0xffff0000u);
    l = pack_bf16x2(v0 - h0, v1 - h1);
}

// bf16 staging: rows of 32 bf16, 80B stride (conflict-free for ldmatrix phases)
static constexpr int ROW_W  = 20;
static constexpr int AH_OFF = 0;
static constexpr int AL_OFF = 128 * ROW_W;
static constexpr int BH_OFF = 2 * 128 * ROW_W;
static constexpr int BL_OFF = 3 * 128 * ROW_W;
static constexpr int STAGE_WORDS = 4 * 128 * ROW_W;       // 40960 B
static constexpr int SMEM_BYTES  = 2 * STAGE_WORDS * 4;   // 81920 B

// ---------------- bf16 slab staging ----------------
__device__ __forceinline__ void stage_slab(
    int slab, int buf, int nsub, int tid, uint32_t smb,
    const bf16* Ah, const bf16* Al, int lda,
    const bf16* Bh, const bf16* Bl, int ldb)
{
    if (slab < nsub) {
        const int k0 = slab << 5;
        const uint32_t sb = smb + (uint32_t)buf * (STAGE_WORDS * 4);
        const int c  = tid & 3;
        const int r0 = tid >> 2;
        #pragma unroll
        for (int h = 0; h < 2; h++) {
            const int r = r0 + h * 64;
            const uint32_t ro = (uint32_t)(r * 80 + c * 16);
            cp16(sb + ro,            Ah + (size_t)r * lda + k0 + c * 8);
            cp16(sb + AL_OFF*4 + ro, Al + (size_t)r * lda + k0 + c * 8);
            cp16(sb + BH_OFF*4 + ro, Bh + (size_t)r * ldb + k0 + c * 8);
            cp16(sb + BL_OFF*4 + ro, Bl + (size_t)r * ldb + k0 + c * 8);
        }
    }
    CP_COMMIT();
}

// ---------------- bf16 gemm core (ldmatrix; R11-proven), 3-product ----------------
__device__ __forceinline__ void gemm_core(
    float acc[2][8][4], uint32_t smb,
    const bf16* Ah, const bf16* Al, int lda,
    const bf16* Bh, const bf16* Bl, int ldb,
    int nsub, int tid)
{
    const int wid  = tid >> 5;
    const int lane = tid & 31;
    const int wm = wid & 3;
    const int wn = wid >> 2;
    const uint32_t aLane = (uint32_t)((wm * 32 + (lane & 15)) * 80 + (lane >> 4) * 16);
    const uint32_t bLane = (uint32_t)((wn * 64 + (lane & 7) + ((lane >> 4) << 3)) * 80
                                      + ((lane >> 3) & 1) * 16);

    stage_slab(0, 0, nsub, tid, smb, Ah, Al, lda, Bh, Bl, ldb);
    for (int slab = 0; slab < nsub; ++slab) {
        stage_slab(slab + 1, (slab + 1) & 1, nsub, tid, smb, Ah, Al, lda, Bh, Bl, ldb);
        CP_WAIT(1);
        __syncthreads();

        const uint32_t sb = smb + (uint32_t)(slab & 1) * (STAGE_WORDS * 4);
        const uint32_t aH = sb + AH_OFF * 4 + aLane;
        const uint32_t aL = sb + AL_OFF * 4 + aLane;
        const uint32_t bH = sb + BH_OFF * 4 + bLane;
        const uint32_t bL = sb + BL_OFF * 4 + bLane;

        #pragma unroll
        for (int s = 0; s < 2; s++) {
            const uint32_t so = (uint32_t)(s * 32);
            uint32_t ah[2][4], al[2][4], bh[8][2];
            #pragma unroll
            for (int mi = 0; mi < 2; mi++) {
                ldsm4(aH + mi * 1280 + so, ah[mi][0], ah[mi][1], ah[mi][2], ah[mi][3]);
                ldsm4(aL + mi * 1280 + so, al[mi][0], al[mi][1], al[mi][2], al[mi][3]);
            }
            #pragma unroll
            for (int nb = 0; nb < 4; nb++) {
                uint32_t t0, t1, t2, t3;
                ldsm4(bH + nb * 1280 + so, t0, t1, t2, t3);
                bh[nb*2][0]   = t0; bh[nb*2][1]   = t1;
                bh[nb*2+1][0] = t2; bh[nb*2+1][1] = t3;
            }
            // pass 1: hh
            #pragma unroll
            for (int ni = 0; ni < 8; ni++)
                #pragma unroll
                for (int mi = 0; mi < 2; mi++)
                    mma16816(acc[mi][ni], ah[mi], bh[ni]);
            // pass 2: lh
            #pragma unroll
            for (int ni = 0; ni < 8; ni++)
                #pragma unroll
                for (int mi = 0; mi < 2; mi++)
                    mma16816(acc[mi][ni], al[mi], bh[ni]);
            // pass 3: hl
            #pragma unroll
            for (int nb = 0; nb < 4; nb++) {
                uint32_t u0, u1, u2, u3;
                ldsm4(bL + nb * 1280 + so, u0, u1, u2, u3);
                uint32_t bl0[2] = { u0, u1 };
                uint32_t bl1[2] = { u2, u3 };
                #pragma unroll
                for (int mi = 0; mi < 2; mi++) {
                    mma16816(acc[mi][nb*2],   ah[mi], bl0);
                    mma16816(acc[mi][nb*2+1], ah[mi], bl1);
                }
            }
        }
        __syncthreads();
    }
    CP_WAIT(0);
    __syncthreads();
}

// ---------------------------------------------------------------------------
// generic GEMM kernel:
// EPI: 1 (+bias[row or col]) split-bf16 | 2 BN+bias+residual fp32
//      3 affinity: u = exp(v-40) split-bf16 store + row-partial sums to spart
//      4 apply: normalize by spart row-sum, split-bf16 store
// ---------------------------------------------------------------------------
template<int EPI>
__global__ void __launch_bounds__(256, 2)
mma_gemm(const bf16* __restrict__ Ah, const bf16* __restrict__ Al, int lda, long sA,
         const bf16* __restrict__ Bh, const bf16* __restrict__ Bl, int ldb, long sB,
         int K,
         float* __restrict__ Cf, bf16* __restrict__ Ch, bf16* __restrict__ Cl,
         int ldc, long sC,
         const float* __restrict__ bias, int bias_col,
         const float* __restrict__ gamma, const float* __restrict__ beta,
         const float* __restrict__ mean,  const float* __restrict__ var,
         const float* __restrict__ resid, float* __restrict__ spart)
{
    extern __shared__ uint32_t s_pipe[];
    const int tid  = threadIdx.x;
    const int wid  = tid >> 5;
    const int lane = tid & 31;
    const int gid  = lane >> 2;
    const int tidg = lane & 3;
    const int bi = blockIdx.y * 128;
    const int bj = blockIdx.x * 128;
    const int b  = blockIdx.z;
    Ah += (size_t)b * sA + (size_t)bi * lda;
    Al += (size_t)b * sA + (size_t)bi * lda;
    Bh += (size_t)b * sB + (size_t)bj * ldb;
    Bl += (size_t)b * sB + (size_t)bj * ldb;

    const uint32_t smb = smem_u32(s_pipe);
    const int wm = wid & 3;
    const int wn = wid >> 2;

    float acc[2][8][4];
    #pragma unroll
    for (int mi = 0; mi < 2; mi++)
        #pragma unroll
        for (int ni = 0; ni < 8; ni++)
            #pragma unroll
            for (int e = 0; e < 4; e++) acc[mi][ni][e] = 0.f;

    gemm_core(acc, smb, Ah, Al, lda, Bh, Bl, ldb, K >> 5, tid);

    float rsum[2][2] = {{0.f, 0.f}, {0.f, 0.f}};   // EPI==3 row partials

    #pragma unroll
    for (int mi = 0; mi < 2; mi++) {
        #pragma unroll
        for (int h = 0; h < 2; h++) {
            const int gi = bi + wm * 32 + mi * 16 + gid + 8 * h;
            float scale = 1.f, shift = 0.f;
            if (EPI == 1 && !bias_col && bias) shift = bias[gi];
            if (EPI == 2) {
                const float sc = gamma[gi] * rsqrtf(var[gi] + 1e-5f);
                scale = sc;
                shift = (bias[gi] - mean[gi]) * sc + beta[gi];
            }
            if (EPI == 4) {
                const float4* sp = (const float4*)(spart + ((size_t)b * Nn + gi) * 8);
                const float4 s0 = sp[0];
                const float4 s1 = sp[1];
                scale = 1.f / (s0.x + s0.y + s0.z + s0.w +
                               s1.x + s1.y + s1.z + s1.w);
            }
            #pragma unroll
            for (int ni = 0; ni < 8; ni++) {
                const int gj = bj + wn * 64 + ni * 8 + tidg * 2;
                const size_t off = (size_t)b * sC + (size_t)gi * ldc + gj;
                float v0 = acc[mi][ni][2*h];
                float v1 = acc[mi][ni][2*h + 1];
                if (EPI == 3) {
                    v0 = __expf(v0 - 40.f);
                    v1 = __expf(v1 - 40.f);
                    rsum[mi][h] += v0 + v1;
                } else if (EPI == 4) {
                    v0 *= scale;
                    v1 *= scale;
                } else if (EPI == 1) {
                    if (bias_col && bias) { v0 += bias[gj]; v1 += bias[gj + 1]; }
                    else                  { v0 += shift;    v1 += shift; }
                }
                if (EPI == 2) {
                    const float2 r2 = *(const float2*)(resid + off);
                    *(float2*)(Cf + off) = make_float2(v0 * scale + shift + r2.x,
                                                       v1 * scale + shift + r2.y);
                } else {
                    uint32_t hw, lw;
                    split_pair(v0, v1, hw, lw);
                    *(uint32_t*)(Ch + off) = hw;
                    *(uint32_t*)(Cl + off) = lw;
                }
            }
        }
    }

    if (EPI == 3) {
        // reduce row partials: over tidg quad, then across the 2 wn warps via smem
        float* red = reinterpret_cast<float*>(s_pipe);   // [128][2]
        #pragma unroll
        for (int mi = 0; mi < 2; mi++)
            #pragma unroll
            for (int h = 0; h < 2; h++) {
                float v = rsum[mi][h];
                v += __shfl_xor_sync(0xffffffffu, v, 1);
                v += __shfl_xor_sync(0xffffffffu, v, 2);
                if (tidg == 0) {
                    const int rl = wm * 32 + mi * 16 + gid + 8 * h;
                    red[rl * 2 + wn] = v;
                }
            }
        __syncthreads();
        if (tid < 128)
            spart[((size_t)b * Nn + bi + tid) * 8 + blockIdx.x] = red[tid*2] + red[tid*2 + 1];
    }
}

// ---------------------------------------------------------------------------
// merged projection kernel
// ---------------------------------------------------------------------------
__global__ void __launch_bounds__(256, 2)
mma_proj(const bf16* __restrict__ xTh, const bf16* __restrict__ xTl,
         const bf16* __restrict__ Wh,  const bf16* __restrict__ Wl,
         bf16* __restrict__ xth_h, bf16* __restrict__ xth_l,
         bf16* __restrict__ xphi_h, bf16* __restrict__ xphi_l,
         bf16* __restrict__ xg_h,  bf16* __restrict__ xg_l,
         const float* __restrict__ thb, const float* __restrict__ phb,
         const float* __restrict__ gb)
{
    extern __shared__ uint32_t s_pipe[];
    const int tid  = threadIdx.x;
    const int wid  = tid >> 5;
    const int lane = tid & 31;
    const int gid  = lane >> 2;
    const int tidg = lane & 3;
    const int px = blockIdx.x >> 1;
    const int bj = (blockIdx.x & 1) * 128;
    const int bi = blockIdx.y * 128;
    const int b  = blockIdx.z;
    const bf16* Ah = xTh + (size_t)b * Nn * Cc + (size_t)bi * Cc;
    const bf16* Al = xTl + (size_t)b * Nn * Cc + (size_t)bi * Cc;
    const bf16* Bh = Wh + (size_t)px * Ci * Cc + (size_t)bj * Cc;
    const bf16* Bl = Wl + (size_t)px * Ci * Cc + (size_t)bj * Cc;
    const float* bias = (px == 0) ? thb : (px == 1) ? phb : gb;

    const uint32_t smb = smem_u32(s_pipe);
    const int wm = wid & 3;
    const int wn = wid >> 2;

    float acc[2][8][4];
    #pragma unroll
    for (int mi = 0; mi < 2; mi++)
        #pragma unroll
        for (int ni = 0; ni < 8; ni++)
            #pragma unroll
            for (int e = 0; e < 4; e++) acc[mi][ni][e] = 0.f;

    gemm_core(acc, smb, Ah, Al, Cc, Bh, Bl, Cc, Cc >> 5, tid);

    if (px == 0) {
        #pragma unroll
        for (int mi = 0; mi < 2; mi++)
            #pragma unroll
            for (int h = 0; h < 2; h++) {
                const int gi = bi + wm * 32 + mi * 16 + gid + 8 * h;
                #pragma unroll
                for (int ni = 0; ni < 8; ni++) {
                    const int gj = bj + wn * 64 + ni * 8 + tidg * 2;
                    const size_t off = ((size_t)b * Nn + gi) * Ci + gj;
                    const float v0 = acc[mi][ni][2*h]     + bias[gj];
                    const float v1 = acc[mi][ni][2*h + 1] + bias[gj + 1];
                    uint32_t hw, lw;
                    split_pair(v0, v1, hw, lw);
                    *(uint32_t*)(xth_h + off) = hw;
                    *(uint32_t*)(xth_l + off) = lw;
                }
            }
        return;
    }

    float* ep = reinterpret_cast<float*>(s_pipe);  // [128][65]
    for (int ch = 0; ch < 2; ++ch) {
        if (wn == ch) {
            #pragma unroll
            for (int mi = 0; mi < 2; mi++)
                #pragma unroll
                for (int h = 0; h < 2; h++) {
                    const int r = wm * 32 + mi * 16 + gid + 8 * h;
                    #pragma unroll
                    for (int ni = 0; ni < 8; ni++) {
                        const int c = ni * 8 + tidg * 2;
                        ep[r * 65 + c]     = acc[mi][ni][2*h];
                        ep[r * 65 + c + 1] = acc[mi][ni][2*h + 1];
                    }
                }
        }
        __syncthreads();
        if (px == 1) {
            for (int o = tid; o < 2048; o += 256) {
                const int cl = o & 63;
                const int wp = o >> 6;
                const int r0 = 2 * wp;
                float v = fmaxf(fmaxf(ep[r0 * 65 + cl],        ep[(r0 + 1) * 65 + cl]),
                                fmaxf(ep[(r0 + 64) * 65 + cl], ep[(r0 + 65) * 65 + cl]));
                const int gci = bj + ch * 64 + cl;
                v += bias[gci];
                const int m = 32 * blockIdx.y + wp;
                const size_t off = ((size_t)b * Mm + m) * Ci + gci;
                const bf16 hh = __float2bfloat16(v);
                xphi_h[off] = hh;
                xphi_l[off] = __float2bfloat16(v - __bfloat162float(hh));
            }
        } else {
            for (int o = tid; o < 2048; o += 256) {
                const int wp = o & 31;
                const int cl = o >> 5;
                const int r0 = 2 * wp;
                float v = fmaxf(fmaxf(ep[r0 * 65 + cl],        ep[(r0 + 1) * 65 + cl]),
                                fmaxf(ep[(r0 + 64) * 65 + cl], ep[(r0 + 65) * 65 + cl]));
                const int gci = bj + ch * 64 + cl;
                v += bias[gci];
                const int m = 32 * blockIdx.y + wp;
                const size_t off = ((size_t)b * Ci + gci) * Mm + m;
                const bf16 hh = __float2bfloat16(v);
                xg_h[off] = hh;
                xg_l[off] = __float2bfloat16(v - __bfloat162float(hh));
            }
        }
        __syncthreads();
    }
}

// ---------------------------------------------------------------------------
// helpers
// ---------------------------------------------------------------------------
__global__ void __launch_bounds__(256) split_all(
    const float* __restrict__ thw, const float* __restrict__ phw,
    const float* __restrict__ gw,  const float* __restrict__ ww,
    bf16* __restrict__ wcat_h, bf16* __restrict__ wcat_l,
    bf16* __restrict__ ww_h,   bf16* __restrict__ ww_l)
{
    int i = blockIdx.x * 256 + threadIdx.x;
    int seg = i >> 17;
    int j   = i & 131071;
    const float* src = (seg == 0) ? thw : (seg == 1) ? phw : (seg == 2) ? gw : ww;
    float v = src[j];
    bf16 hh = __float2bfloat16(v);
    bf16 ll = __float2bfloat16(v - __bfloat162float(hh));
    if (seg < 3) { wcat_h[seg * 131072 + j] = hh; wcat_l[seg * 131072 + j] = ll; }
    else         { ww_h[j] = hh;                  ww_l[j] = ll; }
}

__global__ void tsplit_x(const float* __restrict__ x, bf16* __restrict__ th, bf16* __restrict__ tl)
{
    __shared__ float t[32][33];
    int b = blockIdx.z, n0 = blockIdx.x * 32, c0 = blockIdx.y * 32;
    const float* xp = x + ((size_t)b * Cc + c0) * Nn + n0;
    for (int i = threadIdx.y; i < 32; i += 8)
        t[i][threadIdx.x] = xp[(size_t)i * Nn + threadIdx.x];
    __syncthreads();
    size_t ob = ((size_t)b * Nn + n0) * Cc + c0;
    for (int i = threadIdx.y; i < 32; i += 8) {
        float v = t[threadIdx.x][i];
        bf16 hh = __float2bfloat16(v);
        th[ob + (size_t)i * Cc + threadIdx.x] = hh;
        tl[ob + (size_t)i * Cc + threadIdx.x] = __float2bfloat16(v - __bfloat162float(hh));
    }
}

// ---------------------------------------------------------------------------
extern "C" void kernel_launch(void* const* d_in, const int* in_sizes, int n_in,
                              void* d_out, int out_size)
{
    const float* x     = (const float*)d_in[0];
    const float* gw    = (const float*)d_in[1];
    const float* gb    = (const float*)d_in[2];
    const float* thw   = (const float*)d_in[3];
    const float* thb   = (const float*)d_in[4];
    const float* phw   = (const float*)d_in[5];
    const float* phb   = (const float*)d_in[6];
    const float* ww    = (const float*)d_in[7];
    const float* wb    = (const float*)d_in[8];
    const float* gamma = (const float*)d_in[9];
    const float* beta  = (const float*)d_in[10];
    const float* mean  = (const float*)d_in[11];
    const float* var   = (const float*)d_in[12];
    float* out = (float*)d_out;

    static int smem_set = 0;
    if (!smem_set) {
        cudaFuncSetAttribute((const void*)mma_gemm<2>, cudaFuncAttributeMaxDynamicSharedMemorySize, SMEM_BYTES);
        cudaFuncSetAttribute((const void*)mma_gemm<3>, cudaFuncAttributeMaxDynamicSharedMemorySize, SMEM_BYTES);
        cudaFuncSetAttribute((const void*)mma_gemm<4>, cudaFuncAttributeMaxDynamicSharedMemorySize, SMEM_BYTES);
        cudaFuncSetAttribute((const void*)mma_proj,    cudaFuncAttributeMaxDynamicSharedMemorySize, SMEM_BYTES);
        smem_set = 1;
    }

#define GA(v, s) void* v; cudaGetSymbolAddress(&v, s)
    GA(xT_h, d_xT_h);     GA(xT_l, d_xT_l);
    GA(wcat_h, d_wcat_h); GA(wcat_l, d_wcat_l);
    GA(ww_h, d_ww_h);     GA(ww_l, d_ww_l);
    GA(xth_h, d_xth_h);   GA(xth_l, d_xth_l);
    GA(xphi_h, d_xphi_h); GA(xphi_l, d_xphi_l);
    GA(xg_h, d_xg_h);     GA(xg_l, d_xg_l);
    GA(u_h, d_u_h);       GA(u_l, d_u_l);
    GA(spart, d_spart);
    GA(y_h, d_y_h);       GA(y_l, d_y_l);
#undef GA

    // 0: weight splits
    split_all<<<(4 * Ci * Cc) / 256, 256>>>(
        thw, phw, gw, ww,
        (bf16*)wcat_h, (bf16*)wcat_l, (bf16*)ww_h, (bf16*)ww_l);

    // 1: x transpose + split -> xT [b][n][c]
    tsplit_x<<<dim3(Nn/32, Cc/32, Bb), dim3(32, 8)>>>(x, (bf16*)xT_h, (bf16*)xT_l);

    // 2: merged projections
    mma_proj<<<dim3(6, Nn/128, Bb), 256, SMEM_BYTES>>>(
        (bf16*)xT_h, (bf16*)xT_l, (bf16*)wcat_h, (bf16*)wcat_l,
        (bf16*)xth_h, (bf16*)xth_l, (bf16*)xphi_h, (bf16*)xphi_l,
        (bf16*)xg_h, (bf16*)xg_l, thb, phb, gb);

    // 3: affinity: u[n,m] = exp(theta.phi - 40), split-bf16 + row partial sums
    mma_gemm<3><<<dim3(Mm/128, Nn/128, Bb), 256, SMEM_BYTES>>>(
        (bf16*)xth_h, (bf16*)xth_l, Ci, (long)Nn*Ci,
        (bf16*)xphi_h, (bf16*)xphi_l, Ci, (long)Mm*Ci, Ci,
        nullptr, (bf16*)u_h, (bf16*)u_l, Mm, (long)Nn*Mm,
        nullptr, 0, nullptr, nullptr, nullptr, nullptr, nullptr, (float*)spart);

    // 4: apply (fused normalization): y[n,ci] = (u.g)/s, all-bf16 core
    mma_gemm<4><<<dim3(Ci/128, Nn/128, Bb), 256, SMEM_BYTES>>>(
        (bf16*)u_h, (bf16*)u_l, Mm, (long)Nn*Mm,
        (bf16*)xg_h, (bf16*)xg_l, Mm, (long)Ci*Mm, Mm,
        nullptr, (bf16*)y_h, (bf16*)y_l, Ci, (long)Nn*Ci,
        nullptr, 0, nullptr, nullptr, nullptr, nullptr, nullptr, (float*)spart);

    // 5: out: BN(conv) + residual  (3-product split)
    mma_gemm<2><<<dim3(Nn/128, Cc/128, Bb), 256, SMEM_BYTES>>>(
        (bf16*)ww_h, (bf16*)ww_l, Ci, 0,
        (bf16*)y_h, (bf16*)y_l, Ci, (long)Nn*Ci, Ci,
        out, nullptr, nullptr, Nn, (long)Cc*Nn,
        wb, 0, gamma, beta, mean, var, x, nullptr);
}

// round 16
// speedup vs baseline: 1.0074x; 1.0074x over previous
#include <cuda_runtime.h>
#include <cuda_bf16.h>
#include <cstdint>

#define Bb 8
#define Cc 512
#define Ci 256
#define Nn 4096
#define Mm 1024

using bf16 = __nv_bfloat16;

// ---------------- device scratch (static; no allocation allowed) ----------------
__device__ __align__(128) bf16 d_xT_h[(size_t)Bb*Nn*Cc], d_xT_l[(size_t)Bb*Nn*Cc];   // x^T split [b][n][c]
__device__ __align__(128) bf16 d_wcat_h[3*Ci*Cc], d_wcat_l[3*Ci*Cc];                  // theta|phi|g weights
__device__ __align__(128) bf16 d_ww_h [Cc*Ci], d_ww_l [Cc*Ci];
__device__ __align__(128) bf16 d_xth_h [(size_t)Bb*Nn*Ci], d_xth_l [(size_t)Bb*Nn*Ci]; // theta [b][n][ci]
__device__ __align__(128) bf16 d_xphi_h[(size_t)Bb*Mm*Ci], d_xphi_l[(size_t)Bb*Mm*Ci]; // phi pooled [b][m][ci]
__device__ __align__(128) bf16 d_xg_h  [(size_t)Bb*Ci*Mm], d_xg_l  [(size_t)Bb*Ci*Mm]; // g pooled^T [b][ci][m]
__device__ __align__(128) bf16 d_u_h   [(size_t)Bb*Nn*Mm], d_u_l[(size_t)Bb*Nn*Mm];   // u = exp(logit-40), split
__device__ __align__(128) float d_spart[(size_t)Bb*Nn*8];                               // row partial sums (8 j-tiles)
__device__ __align__(128) bf16 d_y_h   [(size_t)Bb*Nn*Ci], d_y_l[(size_t)Bb*Nn*Ci];    // y [b][n][ci]

// ---------------- PTX helpers (baseline sm_80+ ISA only) ----------------
__device__ __forceinline__ uint32_t smem_u32(const void* p) {
    uint32_t a;
    asm("{ .reg .u64 t; cvta.to.shared.u64 t, %1; cvt.u32.u64 %0, t; }" : "=r"(a) : "l"(p));
    return a;
}
__device__ __forceinline__ void cp16(uint32_t dst, const void* src) {
    asm volatile("cp.async.cg.shared.global [%0], [%1], 16;" :: "r"(dst), "l"(src));
}
#define CP_COMMIT() asm volatile("cp.async.commit_group;" ::: "memory")
#define CP_WAIT(n)  asm volatile("cp.async.wait_group %0;" :: "n"(n) : "memory")

__device__ __forceinline__ void mma16816(float* c, const uint32_t* a, const uint32_t* b) {
    asm volatile("mma.sync.aligned.m16n8k16.row.col.f32.bf16.bf16.f32 "
                 "{%0,%1,%2,%3}, {%4,%5,%6,%7}, {%8,%9}, {%0,%1,%2,%3};"
                 : "+f"(c[0]), "+f"(c[1]), "+f"(c[2]), "+f"(c[3])
                 : "r"(a[0]), "r"(a[1]), "r"(a[2]), "r"(a[3]), "r"(b[0]), "r"(b[1]));
}
__device__ __forceinline__ void ldsm4(uint32_t addr, uint32_t& r0, uint32_t& r1,
                                      uint32_t& r2, uint32_t& r3) {
    asm volatile("ldmatrix.sync.aligned.m8n8.x4.shared.b16 {%0,%1,%2,%3}, [%4];"
                 : "=r"(r0), "=r"(r1), "=r"(r2), "=r"(r3) : "r"(addr));
}

// bf16 staging: rows of 32 bf16, 80B stride (conflict-free for ldmatrix phases)
static constexpr int ROW_W  = 20;
static constexpr int AH_OFF = 0;
static constexpr int AL_OFF = 128 * ROW_W;
static constexpr int BH_OFF = 2 * 128 * ROW_W;
static constexpr int BL_OFF = 3 * 128 * ROW_W;
static constexpr int STAGE_WORDS = 4 * 128 * ROW_W;       // 40960 B
static constexpr int SMEM_BYTES  = 2 * STAGE_WORDS * 4;   // 81920 B

// ---------------- bf16 slab staging ----------------
__device__ __forceinline__ void stage_slab(
    int slab, int buf, int nsub, int tid, uint32_t smb,
    const bf16* Ah, const bf16* Al, int lda,
    const bf16* Bh, const bf16* Bl, int ldb)
{
    if (slab < nsub) {
        const int k0 = slab << 5;
        const uint32_t sb = smb + (uint32_t)buf * (STAGE_WORDS * 4);
        const int c  = tid & 3;
        const int r0 = tid >> 2;
        #pragma unroll
        for (int h = 0; h < 2; h++) {
            const int r = r0 + h * 64;
            const uint32_t ro = (uint32_t)(r * 80 + c * 16);
            cp16(sb + ro,            Ah + (size_t)r * lda + k0 + c * 8);
            cp16(sb + AL_OFF*4 + ro, Al + (size_t)r * lda + k0 + c * 8);
            cp16(sb + BH_OFF*4 + ro, Bh + (size_t)r * ldb + k0 + c * 8);
            cp16(sb + BL_OFF*4 + ro, Bl + (size_t)r * ldb + k0 + c * 8);
        }
    }
    CP_COMMIT();
}

// ---------------- bf16 gemm core (ldmatrix; R11-proven), 3-product ----------------
__device__ __forceinline__ void gemm_core(
    float acc[2][8][4], uint32_t smb,
    const bf16* Ah, const bf16* Al, int lda,
    const bf16* Bh, const bf16* Bl, int ldb,
    int nsub, int tid)
{
    const int wid  = tid >> 5;
    const int lane = tid & 31;
    const int wm = wid & 3;
    const int wn = wid >> 2;
    const uint32_t aLane = (uint32_t)((wm * 32 + (lane & 15)) * 80 + (lane >> 4) * 16);
    const uint32_t bLane = (uint32_t)((wn * 64 + (lane & 7) + ((lane >> 4) << 3)) * 80
                                      + ((lane >> 3) & 1) * 16);

    stage_slab(0, 0, nsub, tid, smb, Ah, Al, lda, Bh, Bl, ldb);
    for (int slab = 0; slab < nsub; ++slab) {
        stage_slab(slab + 1, (slab + 1) & 1, nsub, tid, smb, Ah, Al, lda, Bh, Bl, ldb);
        CP_WAIT(1);
        __syncthreads();

        const uint32_t sb = smb + (uint32_t)(slab & 1) * (STAGE_WORDS * 4);
        const uint32_t aH = sb + AH_OFF * 4 + aLane;
        const uint32_t aL = sb + AL_OFF * 4 + aLane;
        const uint32_t bH = sb + BH_OFF * 4 + bLane;
        const uint32_t bL = sb + BL_OFF * 4 + bLane;

        #pragma unroll
        for (int s = 0; s < 2; s++) {
            const uint32_t so = (uint32_t)(s * 32);
            uint32_t ah[2][4], al[2][4], bh[8][2];
            #pragma unroll
            for (int mi = 0; mi < 2; mi++) {
                ldsm4(aH + mi * 1280 + so, ah[mi][0], ah[mi][1], ah[mi][2], ah[mi][3]);
                ldsm4(aL + mi * 1280 + so, al[mi][0], al[mi][1], al[mi][2], al[mi][3]);
            }
            #pragma unroll
            for (int nb = 0; nb < 4; nb++) {
                uint32_t t0, t1, t2, t3;
                ldsm4(bH + nb * 1280 + so, t0, t1, t2, t3);
                bh[nb*2][0]   = t0; bh[nb*2][1]   = t1;
                bh[nb*2+1][0] = t2; bh[nb*2+1][1] = t3;
            }
            // pass 1: hh
            #pragma unroll
            for (int ni = 0; ni < 8; ni++)
                #pragma unroll
                for (int mi = 0; mi < 2; mi++)
                    mma16816(acc[mi][ni], ah[mi], bh[ni]);
            // pass 2: lh
            #pragma unroll
            for (int ni = 0; ni < 8; ni++)
                #pragma unroll
                for (int mi = 0; mi < 2; mi++)
                    mma16816(acc[mi][ni], al[mi], bh[ni]);
            // pass 3: hl
            #pragma unroll
            for (int nb = 0; nb < 4; nb++) {
                uint32_t u0, u1, u2, u3;
                ldsm4(bL + nb * 1280 + so, u0, u1, u2, u3);
                uint32_t bl0[2] = { u0, u1 };
                uint32_t bl1[2] = { u2, u3 };
                #pragma unroll
                for (int mi = 0; mi < 2; mi++) {
                    mma16816(acc[mi][nb*2],   ah[mi], bl0);
                    mma16816(acc[mi][nb*2+1], ah[mi], bl1);
                }
            }
        }
        __syncthreads();
    }
    CP_WAIT(0);
    __syncthreads();
}

// ---------------------------------------------------------------------------
// generic GEMM kernel:
// EPI: 1 (+bias[row or col]) split-bf16 | 2 BN+bias+residual fp32
//      3 affinity: u = exp(v-40) split-bf16 store + row-partial sums to spart
//      4 apply: normalize by spart row-sum, split-bf16 store
// ---------------------------------------------------------------------------
template<int EPI>
__global__ void __launch_bounds__(256, 2)
mma_gemm(const bf16* __restrict__ Ah, const bf16* __restrict__ Al, int lda, long sA,
         const bf16* __restrict__ Bh, const bf16* __restrict__ Bl, int ldb, long sB,
         int K,
         float* __restrict__ Cf, bf16* __restrict__ Ch, bf16* __restrict__ Cl,
         int ldc, long sC,
         const float* __restrict__ bias, int bias_col,
         const float* __restrict__ gamma, const float* __restrict__ beta,
         const float* __restrict__ mean,  const float* __restrict__ var,
         const float* __restrict__ resid, float* __restrict__ spart)
{
    extern __shared__ uint32_t s_pipe[];
    const int tid  = threadIdx.x;
    const int wid  = tid >> 5;
    const int lane = tid & 31;
    const int gid  = lane >> 2;
    const int tidg = lane & 3;
    const int bi = blockIdx.y * 128;
    const int bj = blockIdx.x * 128;
    const int b  = blockIdx.z;
    Ah += (size_t)b * sA + (size_t)bi * lda;
    Al += (size_t)b * sA + (size_t)bi * lda;
    Bh += (size_t)b * sB + (size_t)bj * ldb;
    Bl += (size_t)b * sB + (size_t)bj * ldb;

    const uint32_t smb = smem_u32(s_pipe);
    const int wm = wid & 3;
    const int wn = wid >> 2;

    float acc[2][8][4];
    #pragma unroll
    for (int mi = 0; mi < 2; mi++)
        #pragma unroll
        for (int ni = 0; ni < 8; ni++)
            #pragma unroll
            for (int e = 0; e < 4; e++) acc[mi][ni][e] = 0.f;

    gemm_core(acc, smb, Ah, Al, lda, Bh, Bl, ldb, K >> 5, tid);

    float rsum[2][2] = {{0.f, 0.f}, {0.f, 0.f}};   // EPI==3 row partials

    #pragma unroll
    for (int mi = 0; mi < 2; mi++) {
        #pragma unroll
        for (int h = 0; h < 2; h++) {
            const int gi = bi + wm * 32 + mi * 16 + gid + 8 * h;
            float scale = 1.f, shift = 0.f;
            if (EPI == 1 && !bias_col && bias) shift = bias[gi];
            if (EPI == 2) {
                const float sc = gamma[gi] * rsqrtf(var[gi] + 1e-5f);
                scale = sc;
                shift = (bias[gi] - mean[gi]) * sc + beta[gi];
            }
            if (EPI == 4) {
                const float4* sp = (const float4*)(spart + ((size_t)b * Nn + gi) * 8);
                const float4 s0 = sp[0];
                const float4 s1 = sp[1];
                scale = 1.f / (s0.x + s0.y + s0.z + s0.w +
                               s1.x + s1.y + s1.z + s1.w);
            }
            #pragma unroll
            for (int ni = 0; ni < 8; ni++) {
                const int gj = bj + wn * 64 + ni * 8 + tidg * 2;
                const size_t off = (size_t)b * sC + (size_t)gi * ldc + gj;
                float v0 = acc[mi][ni][2*h];
                float v1 = acc[mi][ni][2*h + 1];
                if (EPI == 3) {
                    v0 = __expf(v0 - 40.f);
                    v1 = __expf(v1 - 40.f);
                    rsum[mi][h] += v0 + v1;
                } else if (EPI == 4) {
                    v0 *= scale;
                    v1 *= scale;
                } else if (EPI == 1) {
                    if (bias_col && bias) { v0 += bias[gj]; v1 += bias[gj + 1]; }
                    else                  { v0 += shift;    v1 += shift; }
                }
                if (EPI == 2) {
                    const float2 r2 = *(const float2*)(resid + off);
                    *(float2*)(Cf + off) = make_float2(v0 * scale + shift + r2.x,
                                                       v1 * scale + shift + r2.y);
                } else {
                    const bf16 h0 = __float2bfloat16(v0);
                    const bf16 h1 = __float2bfloat16(v1);
                    __nv_bfloat162 hv; hv.x = h0; hv.y = h1;
                    __nv_bfloat162 lv;
                    lv.x = __float2bfloat16(v0 - __bfloat162float(h0));
                    lv.y = __float2bfloat16(v1 - __bfloat162float(h1));
                    *(__nv_bfloat162*)(Ch + off) = hv;
                    *(__nv_bfloat162*)(Cl + off) = lv;
                }
            }
        }
    }

    if (EPI == 3) {
        // reduce row partials: over tidg quad, then across the 2 wn warps via smem
        float* red = reinterpret_cast<float*>(s_pipe);   // [128][2]
        #pragma unroll
        for (int mi = 0; mi < 2; mi++)
            #pragma unroll
            for (int h = 0; h < 2; h++) {
                float v = rsum[mi][h];
                v += __shfl_xor_sync(0xffffffffu, v, 1);
                v += __shfl_xor_sync(0xffffffffu, v, 2);
                if (tidg == 0) {
                    const int rl = wm * 32 + mi * 16 + gid + 8 * h;
                    red[rl * 2 + wn] = v;
                }
            }
        __syncthreads();
        if (tid < 128)
            spart[((size_t)b * Nn + bi + tid) * 8 + blockIdx.x] = red[tid*2] + red[tid*2 + 1];
    }
}

// ---------------------------------------------------------------------------
// merged projection kernel (R14-identical)
// ---------------------------------------------------------------------------
__global__ void __launch_bounds__(256, 2)
mma_proj(const bf16* __restrict__ xTh, const bf16* __restrict__ xTl,
         const bf16* __restrict__ Wh,  const bf16* __restrict__ Wl,
         bf16* __restrict__ xth_h, bf16* __restrict__ xth_l,
         bf16* __restrict__ xphi_h, bf16* __restrict__ xphi_l,
         bf16* __restrict__ xg_h,  bf16* __restrict__ xg_l,
         const float* __restrict__ thb, const float* __restrict__ phb,
         const float* __restrict__ gb)
{
    extern __shared__ uint32_t s_pipe[];
    const int tid  = threadIdx.x;
    const int wid  = tid >> 5;
    const int lane = tid & 31;
    const int gid  = lane >> 2;
    const int tidg = lane & 3;
    const int px = blockIdx.x >> 1;
    const int bj = (blockIdx.x & 1) * 128;
    const int bi = blockIdx.y * 128;
    const int b  = blockIdx.z;
    const bf16* Ah = xTh + (size_t)b * Nn * Cc + (size_t)bi * Cc;
    const bf16* Al = xTl + (size_t)b * Nn * Cc + (size_t)bi * Cc;
    const bf16* Bh = Wh + (size_t)px * Ci * Cc + (size_t)bj * Cc;
    const bf16* Bl = Wl + (size_t)px * Ci * Cc + (size_t)bj * Cc;
    const float* bias = (px == 0) ? thb : (px == 1) ? phb : gb;

    const uint32_t smb = smem_u32(s_pipe);
    const int wm = wid & 3;
    const int wn = wid >> 2;

    float acc[2][8][4];
    #pragma unroll
    for (int mi = 0; mi < 2; mi++)
        #pragma unroll
        for (int ni = 0; ni < 8; ni++)
            #pragma unroll
            for (int e = 0; e < 4; e++) acc[mi][ni][e] = 0.f;

    gemm_core(acc, smb, Ah, Al, Cc, Bh, Bl, Cc, Cc >> 5, tid);

    if (px == 0) {
        #pragma unroll
        for (int mi = 0; mi < 2; mi++)
            #pragma unroll
            for (int h = 0; h < 2; h++) {
                const int gi = bi + wm * 32 + mi * 16 + gid + 8 * h;
                #pragma unroll
                for (int ni = 0; ni < 8; ni++) {
                    const int gj = bj + wn * 64 + ni * 8 + tidg * 2;
                    const size_t off = ((size_t)b * Nn + gi) * Ci + gj;
                    float v0 = acc[mi][ni][2*h]     + bias[gj];
                    float v1 = acc[mi][ni][2*h + 1] + bias[gj + 1];
                    const bf16 h0 = __float2bfloat16(v0);
                    const bf16 h1 = __float2bfloat16(v1);
                    __nv_bfloat162 hv; hv.x = h0; hv.y = h1;
                    __nv_bfloat162 lv;
                    lv.x = __float2bfloat16(v0 - __bfloat162float(h0));
                    lv.y = __float2bfloat16(v1 - __bfloat162float(h1));
                    *(__nv_bfloat162*)(xth_h + off) = hv;
                    *(__nv_bfloat162*)(xth_l + off) = lv;
                }
            }
        return;
    }

    float* ep = reinterpret_cast<float*>(s_pipe);  // [128][65]
    for (int ch = 0; ch < 2; ++ch) {
        if (wn == ch) {
            #pragma unroll
            for (int mi = 0; mi < 2; mi++)
                #pragma unroll
                for (int h = 0; h < 2; h++) {
                    const int r = wm * 32 + mi * 16 + gid + 8 * h;
                    #pragma unroll
                    for (int ni = 0; ni < 8; ni++) {
                        const int c = ni * 8 + tidg * 2;
                        ep[r * 65 + c]     = acc[mi][ni][2*h];
                        ep[r * 65 + c + 1] = acc[mi][ni][2*h + 1];
                    }
                }
        }
        __syncthreads();
        if (px == 1) {
            for (int o = tid; o < 2048; o += 256) {
                const int cl = o & 63;
                const int wp = o >> 6;
                const int r0 = 2 * wp;
                float v = fmaxf(fmaxf(ep[r0 * 65 + cl],        ep[(r0 + 1) * 65 + cl]),
                                fmaxf(ep[(r0 + 64) * 65 + cl], ep[(r0 + 65) * 65 + cl]));
                const int gci = bj + ch * 64 + cl;
                v += bias[gci];
                const int m = 32 * blockIdx.y + wp;
                const size_t off = ((size_t)b * Mm + m) * Ci + gci;
                const bf16 hh = __float2bfloat16(v);
                xphi_h[off] = hh;
                xphi_l[off] = __float2bfloat16(v - __bfloat162float(hh));
            }
        } else {
            for (int o = tid; o < 2048; o += 256) {
                const int wp = o & 31;
                const int cl = o >> 5;
                const int r0 = 2 * wp;
                float v = fmaxf(fmaxf(ep[r0 * 65 + cl],        ep[(r0 + 1) * 65 + cl]),
                                fmaxf(ep[(r0 + 64) * 65 + cl], ep[(r0 + 65) * 65 + cl]));
                const int gci = bj + ch * 64 + cl;
                v += bias[gci];
                const int m = 32 * blockIdx.y + wp;
                const size_t off = ((size_t)b * Ci + gci) * Mm + m;
                const bf16 hh = __float2bfloat16(v);
                xg_h[off] = hh;
                xg_l[off] = __float2bfloat16(v - __bfloat162float(hh));
            }
        }
        __syncthreads();
    }
}

// ---------------------------------------------------------------------------
// fused prep: blocks [0, Nn/32) x-transpose+split; blocks [Nn/32, Nn/32+16) on
// (y==0, z==0) slice handle the 4 weight splits (4*131072 elems / (16*8192)).
// ---------------------------------------------------------------------------
__global__ void prep_all(const float* __restrict__ x,
                         bf16* __restrict__ th, bf16* __restrict__ tl,
                         const float* __restrict__ thw, const float* __restrict__ phw,
                         const float* __restrict__ gw,  const float* __restrict__ ww,
                         bf16* __restrict__ wcat_h, bf16* __restrict__ wcat_l,
                         bf16* __restrict__ ww_h,   bf16* __restrict__ ww_l)
{
    if (blockIdx.x >= Nn/32) {
        if (blockIdx.y != 0 || blockIdx.z != 0) return;
        const int blk = blockIdx.x - Nn/32;            // 0..15
        const int t   = threadIdx.y * 32 + threadIdx.x; // 0..255
        // each block handles 32768 contiguous elems of the 524288-elem range
        for (int k = 0; k < 32768; k += 256) {
            const int i = blk * 32768 + k + t;
            const int seg = i >> 17;
            const int j   = i & 131071;
            const float* src = (seg == 0) ? thw : (seg == 1) ? phw : (seg == 2) ? gw : ww;
            const float v = src[j];
            const bf16 hh = __float2bfloat16(v);
            const bf16 ll = __float2bfloat16(v - __bfloat162float(hh));
            if (seg < 3) { wcat_h[seg * 131072 + j] = hh; wcat_l[seg * 131072 + j] = ll; }
            else         { ww_h[j] = hh;                  ww_l[j] = ll; }
        }
        return;
    }

    __shared__ float t[32][33];
    const int b = blockIdx.z, n0 = blockIdx.x * 32, c0 = blockIdx.y * 32;
    const float* xp = x + ((size_t)b * Cc + c0) * Nn + n0;
    for (int i = threadIdx.y; i < 32; i += 8)
        t[i][threadIdx.x] = xp[(size_t)i * Nn + threadIdx.x];
    __syncthreads();
    const size_t ob = ((size_t)b * Nn + n0) * Cc + c0;
    for (int i = threadIdx.y; i < 32; i += 8) {
        const float v = t[threadIdx.x][i];
        const bf16 hh = __float2bfloat16(v);
        th[ob + (size_t)i * Cc + threadIdx.x] = hh;
        tl[ob + (size_t)i * Cc + threadIdx.x] = __float2bfloat16(v - __bfloat162float(hh));
    }
}

// ---------------------------------------------------------------------------
extern "C" void kernel_launch(void* const* d_in, const int* in_sizes, int n_in,
                              void* d_out, int out_size)
{
    const float* x     = (const float*)d_in[0];
    const float* gw    = (const float*)d_in[1];
    const float* gb    = (const float*)d_in[2];
    const float* thw   = (const float*)d_in[3];
    const float* thb   = (const float*)d_in[4];
    const float* phw   = (const float*)d_in[5];
    const float* phb   = (const float*)d_in[6];
    const float* ww    = (const float*)d_in[7];
    const float* wb    = (const float*)d_in[8];
    const float* gamma = (const float*)d_in[9];
    const float* beta  = (const float*)d_in[10];
    const float* mean  = (const float*)d_in[11];
    const float* var   = (const float*)d_in[12];
    float* out = (float*)d_out;

    static int smem_set = 0;
    if (!smem_set) {
        cudaFuncSetAttribute((const void*)mma_gemm<2>, cudaFuncAttributeMaxDynamicSharedMemorySize, SMEM_BYTES);
        cudaFuncSetAttribute((const void*)mma_gemm<3>, cudaFuncAttributeMaxDynamicSharedMemorySize, SMEM_BYTES);
        cudaFuncSetAttribute((const void*)mma_gemm<4>, cudaFuncAttributeMaxDynamicSharedMemorySize, SMEM_BYTES);
        cudaFuncSetAttribute((const void*)mma_proj,    cudaFuncAttributeMaxDynamicSharedMemorySize, SMEM_BYTES);
        smem_set = 1;
    }

#define GA(v, s) void* v; cudaGetSymbolAddress(&v, s)
    GA(xT_h, d_xT_h);     GA(xT_l, d_xT_l);
    GA(wcat_h, d_wcat_h); GA(wcat_l, d_wcat_l);
    GA(ww_h, d_ww_h);     GA(ww_l, d_ww_l);
    GA(xth_h, d_xth_h);   GA(xth_l, d_xth_l);
    GA(xphi_h, d_xphi_h); GA(xphi_l, d_xphi_l);
    GA(xg_h, d_xg_h);     GA(xg_l, d_xg_l);
    GA(u_h, d_u_h);       GA(u_l, d_u_l);
    GA(spart, d_spart);
    GA(y_h, d_y_h);       GA(y_l, d_y_l);
#undef GA

    // 0: fused prep (x transpose+split, weight splits)
    prep_all<<<dim3(Nn/32 + 16, Cc/32, Bb), dim3(32, 8)>>>(
        x, (bf16*)xT_h, (bf16*)xT_l,
        thw, phw, gw, ww,
        (bf16*)wcat_h, (bf16*)wcat_l, (bf16*)ww_h, (bf16*)ww_l);

    // 1: merged projections
    mma_proj<<<dim3(6, Nn/128, Bb), 256, SMEM_BYTES>>>(
        (bf16*)xT_h, (bf16*)xT_l, (bf16*)wcat_h, (bf16*)wcat_l,
        (bf16*)xth_h, (bf16*)xth_l, (bf16*)xphi_h, (bf16*)xphi_l,
        (bf16*)xg_h, (bf16*)xg_l, thb, phb, gb);

    // 2: affinity: u[n,m] = exp(theta.phi - 40), split-bf16 + row partial sums
    mma_gemm<3><<<dim3(Mm/128, Nn/128, Bb), 256, SMEM_BYTES>>>(
        (bf16*)xth_h, (bf16*)xth_l, Ci, (long)Nn*Ci,
        (bf16*)xphi_h, (bf16*)xphi_l, Ci, (long)Mm*Ci, Ci,
        nullptr, (bf16*)u_h, (bf16*)u_l, Mm, (long)Nn*Mm,
        nullptr, 0, nullptr, nullptr, nullptr, nullptr, nullptr, (float*)spart);

    // 3: apply (fused normalization): y[n,ci] = (u.g)/s
    mma_gemm<4><<<dim3(Ci/128, Nn/128, Bb), 256, SMEM_BYTES>>>(
        (bf16*)u_h, (bf16*)u_l, Mm, (long)Nn*Mm,
        (bf16*)xg_h, (bf16*)xg_l, Mm, (long)Ci*Mm, Mm,
        nullptr, (bf16*)y_h, (bf16*)y_l, Ci, (long)Nn*Ci,
        nullptr, 0, nullptr, nullptr, nullptr, nullptr, nullptr, (float*)spart);

    // 4: out: BN(conv) + residual (3-product split)
    mma_gemm<2><<<dim3(Nn/128, Cc/128, Bb), 256, SMEM_BYTES>>>(
        (bf16*)ww_h, (bf16*)ww_l, Ci, 0,
        (bf16*)y_h, (bf16*)y_l, Ci, (long)Nn*Ci, Ci,
        out, nullptr, nullptr, Nn, (long)Cc*Nn,
        wb, 0, gamma, beta, mean, var, x, nullptr);
}